// round 3
// baseline (speedup 1.0000x reference)
#include <cuda_runtime.h>
#include <stdint.h>

// Problem shape (fixed)
#define BB    64
#define TT    128
#define CIN   2048
#define COUT  2048

// GEMM tiling: CTA 128x128, warp 64x32, k-stage 64, 4-deep cp.async pipeline
#define M_TILE   128
#define N_TILE   128
#define K_STAGE  64
#define STAGES   4
#define KITERS   (CIN / K_STAGE)   // 32

#define A_PITCH      80                              // 64B data + 16B pad (conflict-free)
#define B_STAGE_OFF  (M_TILE * A_PITCH)              // 10240
#define STAGE_BYTES  ((M_TILE + N_TILE) * A_PITCH)   // 20480
#define SMEM_TOTAL   (STAGES * STAGE_BYTES)          // 81920
#define EPI_PITCH    129                             // fp32 staging pitch (odd)
#define BITS_OFF     (M_TILE * EPI_PITCH * 4)        // 66048

// Scratch (static device globals — no runtime allocation)
__device__ int8_t g_A[(size_t)BB * TT * CIN];   // 16 MB: A[b*128+t][c] = spike
__device__ int8_t g_B[(size_t)COUT * CIN];      //  4 MB: B[n][k] = int8(W*mask)

// ---------------------------------------------------------------------------
// helpers
// ---------------------------------------------------------------------------
__device__ __forceinline__ uint32_t smem_u32(const void* p) {
    uint32_t a;
    asm("{ .reg .u64 t; cvta.to.shared.u64 t, %1; cvt.u32.u64 %0, t; }" : "=r"(a) : "l"(p));
    return a;
}
__device__ __forceinline__ void cp_async16(uint32_t dst, const void* src) {
    asm volatile("cp.async.cg.shared.global [%0], [%1], 16;" :: "r"(dst), "l"(src) : "memory");
}
__device__ __forceinline__ void cp_commit() {
    asm volatile("cp.async.commit_group;" ::: "memory");
}
__device__ __forceinline__ void cp_wait2() {
    asm volatile("cp.async.wait_group 2;" ::: "memory");
}
__device__ __forceinline__ void mma_s8(int* c, const uint32_t* a, const uint32_t* bf) {
    asm volatile(
        "mma.sync.aligned.m16n8k32.row.col.s32.s8.s8.s32 "
        "{%0,%1,%2,%3}, {%4,%5,%6,%7}, {%8,%9}, {%0,%1,%2,%3};"
        : "+r"(c[0]), "+r"(c[1]), "+r"(c[2]), "+r"(c[3])
        : "r"(a[0]), "r"(a[1]), "r"(a[2]), "r"(a[3]), "r"(bf[0]), "r"(bf[1]));
}

// ---------------------------------------------------------------------------
// Kernel 1: A = transpose(spikes) to int8.  spikes [b][c][t] f32 -> A[b*128+t][c]
// ---------------------------------------------------------------------------
__global__ void __launch_bounds__(256) pack_a_kernel(const float* __restrict__ spikes) {
    __shared__ float st[32][TT + 1];
    int b = blockIdx.y, c0 = blockIdx.x * 32, tid = threadIdx.x;
    const float* sp = spikes + ((size_t)b * CIN + c0) * TT;
    for (int idx = tid; idx < 32 * TT; idx += 256) {
        int t = idx & 127, c = idx >> 7;
        st[c][t] = sp[(size_t)c * TT + t];
    }
    __syncthreads();
    uint32_t* Ab = (uint32_t*)(g_A + ((size_t)b * TT) * CIN + c0);
    for (int idx = tid; idx < TT * 8; idx += 256) {
        int tt = idx >> 3, j = idx & 7;
        uint32_t v = 0;
#pragma unroll
        for (int q = 0; q < 4; q++)
            v |= (st[j * 4 + q][tt] > 0.5f ? 1u : 0u) << (8 * q);
        Ab[(size_t)tt * (CIN / 4) + j] = v;
    }
}

// ---------------------------------------------------------------------------
// Kernel 2: B = int8(W * mask), K-major (native layout)
// ---------------------------------------------------------------------------
__global__ void __launch_bounds__(256) prep_b_kernel(const float* __restrict__ W,
                                                     const float* __restrict__ Msk) {
    size_t i = ((size_t)blockIdx.x * 256 + threadIdx.x) * 4;
    float4 w = *(const float4*)(W + i);
    float4 m = *(const float4*)(Msk + i);
    int x0 = __float2int_rn(w.x * m.x);
    int x1 = __float2int_rn(w.y * m.y);
    int x2 = __float2int_rn(w.z * m.z);
    int x3 = __float2int_rn(w.w * m.w);
    uint32_t v = (uint32_t)(uint8_t)x0 | ((uint32_t)(uint8_t)x1 << 8) |
                 ((uint32_t)(uint8_t)x2 << 16) | ((uint32_t)(uint8_t)x3 << 24);
    *(uint32_t*)(g_B + i) = v;
}

// ---------------------------------------------------------------------------
// Kernel 3: int8 mma.sync GEMM (128x128 tile, K=2048) + fused integrate/fire/
// reset scan epilogue.  Grid (COUT/128=16, BB=64); 256 threads (8 warps 2x4).
// ---------------------------------------------------------------------------
__device__ __forceinline__ void load_stage(uint32_t sb, int s, size_t M0, int N0) {
    int tid = threadIdx.x;
    uint32_t st = sb + (uint32_t)(s & 3) * STAGE_BYTES;
    int k0 = s * K_STAGE;
    const char* Ab = (const char*)g_A + M0 * CIN + k0;
    const char* Bb = (const char*)g_B + (size_t)N0 * CIN + k0;
#pragma unroll
    for (int i = 0; i < 2; i++) {
        int ch = tid + i * 256;                     // 512 chunks: 128 rows x 4
        int r = ch >> 2, c = ch & 3;
        cp_async16(st + r * A_PITCH + c * 16, Ab + (size_t)r * CIN + c * 16);
    }
#pragma unroll
    for (int i = 0; i < 2; i++) {
        int ch = tid + i * 256;
        int r = ch >> 2, c = ch & 3;
        cp_async16(st + B_STAGE_OFF + r * A_PITCH + c * 16, Bb + (size_t)r * CIN + c * 16);
    }
}

__global__ void __launch_bounds__(256, 1) gemm_scan_kernel(const int* __restrict__ scale_exp,
                                                           const int* __restrict__ texp,
                                                           float* __restrict__ out) {
    extern __shared__ char smem[];
    const uint32_t sb = smem_u32(smem);
    int tid = threadIdx.x, wid = tid >> 5, lane = tid & 31;
    int warpM = wid >> 2, warpN = wid & 3;
    int g = lane >> 2, q = lane & 3;
    int b = blockIdx.y, N0 = blockIdx.x * N_TILE;
    size_t M0 = (size_t)b * TT;

    int acc[4][4][4];
#pragma unroll
    for (int i = 0; i < 4; i++)
#pragma unroll
        for (int j = 0; j < 4; j++)
#pragma unroll
            for (int r = 0; r < 4; r++) acc[i][j][r] = 0;

    // Prologue: 3 stages in flight
    load_stage(sb, 0, M0, N0); cp_commit();
    load_stage(sb, 1, M0, N0); cp_commit();
    load_stage(sb, 2, M0, N0); cp_commit();

    // Per-thread fragment offsets (relative to smem base)
    const int aOff = (warpM * 64 + g) * A_PITCH + q * 4;
    const int bOff = B_STAGE_OFF + (warpN * 32 + g) * A_PITCH + q * 4;

    for (int s = 0; s < KITERS; s++) {
        cp_wait2();                 // own loads of stage s complete
        __syncthreads();            // all threads' loads of s visible; s-1 compute done
        if (s + 3 < KITERS) load_stage(sb, s + 3, M0, N0);
        cp_commit();                // empty groups in tail keep wait arithmetic uniform
        const int stOff = (s & 3) * STAGE_BYTES;
#pragma unroll
        for (int ks = 0; ks < 2; ks++) {
            const int koff = stOff + ks * 32;
            uint32_t af[4][4], bf[4][2];
#pragma unroll
            for (int mt = 0; mt < 4; mt++) {
                const char* p = smem + koff + aOff + mt * (16 * A_PITCH);
                af[mt][0] = *(const uint32_t*)(p);
                af[mt][1] = *(const uint32_t*)(p + 8 * A_PITCH);
                af[mt][2] = *(const uint32_t*)(p + 16);
                af[mt][3] = *(const uint32_t*)(p + 8 * A_PITCH + 16);
            }
#pragma unroll
            for (int nt = 0; nt < 4; nt++) {
                const char* p = smem + koff + bOff + nt * (8 * A_PITCH);
                bf[nt][0] = *(const uint32_t*)(p);
                bf[nt][1] = *(const uint32_t*)(p + 16);
            }
#pragma unroll
            for (int mt = 0; mt < 4; mt++)
#pragma unroll
                for (int nt = 0; nt < 4; nt++)
                    mma_s8(acc[mt][nt], af[mt], bf[nt]);
        }
    }
    __syncthreads();

    // Stage C (rows = t, cols = o) into smem as fp32 (exact: |acc| < 2^19)
    float* sEP = (float*)smem;
#pragma unroll
    for (int mt = 0; mt < 4; mt++) {
        int row = warpM * 64 + mt * 16 + g;
#pragma unroll
        for (int nt = 0; nt < 4; nt++) {
            int col = warpN * 32 + nt * 8 + q * 2;
            sEP[row * EPI_PITCH + col]           = (float)acc[mt][nt][0];
            sEP[row * EPI_PITCH + col + 1]       = (float)acc[mt][nt][1];
            sEP[(row + 8) * EPI_PITCH + col]     = (float)acc[mt][nt][2];
            sEP[(row + 8) * EPI_PITCH + col + 1] = (float)acc[mt][nt][3];
        }
    }
    __syncthreads();

    // Integrate / fire / reset scan: thread o scans its channel over t
    uint32_t* sBits = (uint32_t*)(smem + BITS_OFF);
    if (tid < N_TILE) {
        float scale = exp2f((float)scale_exp[N0 + tid]);
        float thr   = exp2f((float)texp[0]);
        float a = 0.0f;
        uint32_t bits[4] = {0, 0, 0, 0};
#pragma unroll 4
        for (int t = 0; t < TT; t++) {
            a = fmaf(sEP[t * EPI_PITCH + tid], scale, a);
            if (a >= thr) { bits[t >> 5] |= 1u << (t & 31); a = 0.0f; }
        }
        sBits[tid * 4 + 0] = bits[0];
        sBits[tid * 4 + 1] = bits[1];
        sBits[tid * 4 + 2] = bits[2];
        sBits[tid * 4 + 3] = bits[3];
    }
    __syncthreads();

    // Coalesced output: out[b][N0+o][t]
    float* outB = out + ((size_t)b * COUT + N0) * TT;
    for (int e = tid; e < N_TILE * TT; e += 256) {
        int o = e >> 7, t = e & 127;
        outB[(size_t)o * TT + t] = ((sBits[o * 4 + (t >> 5)] >> (t & 31)) & 1) ? 1.0f : 0.0f;
    }
}

// ---------------------------------------------------------------------------
// Inputs: spikes f32 [64,2048,128], weights f32 [2048,2048], mask f32
// [2048,2048], scale_exp i32 [2048], threshold_exp i32 [1].
// Output: f32 [64,2048,128].
// ---------------------------------------------------------------------------
extern "C" void kernel_launch(void* const* d_in, const int* in_sizes, int n_in,
                              void* d_out, int out_size) {
    const float* spikes    = (const float*)d_in[0];
    const float* weights   = (const float*)d_in[1];
    const float* mask      = (const float*)d_in[2];
    const int*   scale_exp = (const int*)d_in[3];
    const int*   texp      = (const int*)d_in[4];
    float*       out       = (float*)d_out;

    cudaFuncSetAttribute(gemm_scan_kernel,
                         cudaFuncAttributeMaxDynamicSharedMemorySize, SMEM_TOTAL);

    pack_a_kernel<<<dim3(CIN / 32, BB), 256>>>(spikes);
    prep_b_kernel<<<(size_t)COUT * CIN / 4 / 256, 256>>>(weights, mask);
    gemm_scan_kernel<<<dim3(COUT / N_TILE, BB), 256, SMEM_TOTAL>>>(scale_exp, texp, out);
}

// round 4
// speedup vs baseline: 2.6675x; 2.6675x over previous
#include <cuda_runtime.h>
#include <stdint.h>

// Problem shape (fixed)
#define BB    64
#define TT    128
#define CIN   2048
#define COUT  2048
#define NRB   256          // COUT/8 block-rows
#define NCB   256          // CIN/8 block-cols
#define KCAP  64           // max kept blocks per block-row (Binom(256,0.1): max ~45)

// Sparse GEMM config
#define CHUNK      8                   // blocks per pipeline stage (64 k-elems)
#define A_STAGE    (CHUNK * TT * 8)    // 8192 B per stage ([j][row][8])
#define NSTAGE     4
#define B_PITCH    528                 // 512 data + 16 pad (conflict-free B frags)
#define B_OFF      (NSTAGE * A_STAGE)             // 32768
#define C_OFF      (B_OFF + 8 * B_PITCH)          // 36992
#define C_PITCH    9                               // fp32 words
#define BITS_OFF   (C_OFF + TT * C_PITCH * 4)     // 41600
#define SMEM_G     (BITS_OFF + 128)               // 41728

// Scratch (static device globals — no runtime allocation)
__device__ __align__(16) int8_t  g_A2[(size_t)NCB * BB * TT * 8]; // 16MB [cb][m][8]
__device__ __align__(16) int8_t  g_Bc[(size_t)NRB * 8 * KCAP * 8];// 1MB  [rb][n][512]
__device__ uint8_t g_cols[NRB * KCAP];
__device__ int     g_nk[NRB];

// ---------------------------------------------------------------------------
// helpers
// ---------------------------------------------------------------------------
__device__ __forceinline__ uint32_t smem_u32(const void* p) {
    uint32_t a;
    asm("{ .reg .u64 t; cvta.to.shared.u64 t, %1; cvt.u32.u64 %0, t; }" : "=r"(a) : "l"(p));
    return a;
}
__device__ __forceinline__ void cp_async16(uint32_t dst, const void* src) {
    asm volatile("cp.async.cg.shared.global [%0], [%1], 16;" :: "r"(dst), "l"(src) : "memory");
}
__device__ __forceinline__ void cp_commit() {
    asm volatile("cp.async.commit_group;" ::: "memory");
}
__device__ __forceinline__ void cp_wait2() {
    asm volatile("cp.async.wait_group 2;" ::: "memory");
}
__device__ __forceinline__ void mma_s8(int* c, const uint32_t* a, const uint32_t* b) {
    asm volatile(
        "mma.sync.aligned.m16n8k32.row.col.s32.s8.s8.s32 "
        "{%0,%1,%2,%3}, {%4,%5,%6,%7}, {%8,%9}, {%0,%1,%2,%3};"
        : "+r"(c[0]), "+r"(c[1]), "+r"(c[2]), "+r"(c[3])
        : "r"(a[0]), "r"(a[1]), "r"(a[2]), "r"(a[3]), "r"(b[0]), "r"(b[1]));
}

// ---------------------------------------------------------------------------
// Kernel 1: spikes [b][c][t] f32 -> A2[cb][b*128+t][8] int8 (block-major)
// Grid (CIN/64=32, BB); 256 threads.
// ---------------------------------------------------------------------------
__global__ void __launch_bounds__(256) pack_a_kernel(const float* __restrict__ spikes) {
    __shared__ float s[64][132];
    int b = blockIdx.y, c0 = blockIdx.x * 64, tid = threadIdx.x;
    const float* sp = spikes + ((size_t)b * CIN + c0) * TT;
#pragma unroll
    for (int i = 0; i < 8; i++) {                 // 2048 float4 loads
        int e = tid + i * 256;
        int c = e >> 5, t4 = e & 31;
        float4 v = *(const float4*)(sp + (size_t)c * TT + t4 * 4);
        *(float4*)&s[c][t4 * 4] = v;
    }
    __syncthreads();
#pragma unroll
    for (int i = 0; i < 4; i++) {                 // 1024 uint2 writes
        int e = tid + i * 256;
        int jb = e >> 7, t = e & 127;
        uint32_t lo = 0, hi = 0;
#pragma unroll
        for (int q = 0; q < 4; q++) {
            lo |= (s[jb * 8 + q][t] > 0.5f ? 1u : 0u) << (8 * q);
            hi |= (s[jb * 8 + 4 + q][t] > 0.5f ? 1u : 0u) << (8 * q);
        }
        uint2 v; v.x = lo; v.y = hi;
        *(uint2*)(g_A2 + ((size_t)((c0 >> 3) + jb) << 16) + ((size_t)b * TT + t) * 8) = v;
    }
}

// ---------------------------------------------------------------------------
// Kernel 2: per block-row, find kept 8x8 blocks; compact weights to
// g_Bc[rb][n][k_compact] int8 (zero padded to KCAP*8).  One CTA per rb.
// ---------------------------------------------------------------------------
__global__ void __launch_bounds__(256) prep_kernel(const float* __restrict__ W,
                                                   const float* __restrict__ M) {
    int rb = blockIdx.x, tid = threadIdx.x;
    __shared__ uint8_t keptf[NCB];
    __shared__ uint8_t colss[KCAP];
    __shared__ int nks;

    int cb = tid;
    bool kept = false;
    for (int e = 0; e < 64 && !kept; e++) {
        int io = e >> 3, jj = e & 7;
        if (M[(size_t)(rb * 8 + io) * CIN + cb * 8 + jj] != 0.0f) kept = true;
    }
    keptf[cb] = kept ? 1 : 0;
    __syncthreads();
    if (tid == 0) {
        int n = 0;
        for (int c = 0; c < NCB; c++)
            if (keptf[c] && n < KCAP) colss[n++] = (uint8_t)c;
        nks = n;
        g_nk[rb] = n;
        for (int k = n; k < KCAP; k++) colss[k] = 0;
    }
    __syncthreads();
    if (tid < KCAP) g_cols[rb * KCAP + tid] = colss[tid];

    int nk8 = nks * 8;
    for (int idx = tid; idx < 8 * KCAP * 8; idx += 256) {
        int n = idx >> 9, kk = idx & 511;
        int8_t val = 0;
        if (kk < nk8) {
            int col = colss[kk >> 3], jj = kk & 7;
            size_t gi = (size_t)(rb * 8 + n) * CIN + col * 8 + jj;
            val = (int8_t)__float2int_rn(W[gi] * M[gi]);
        }
        g_Bc[(size_t)rb * 4096 + n * 512 + kk] = val;
    }
}

// ---------------------------------------------------------------------------
// Kernel 3: block-sparse int8 MMA GEMM + fused integrate/fire/reset scan.
// CTA = (rb, b): M=128 (batch time series), N=8 (block-row), K = nk*8 gathered.
// 128 threads = 4 warps, each warp two m16n8k32 tiles.
// ---------------------------------------------------------------------------
__device__ __forceinline__ void gather_stage(uint32_t sb, int c, const uint8_t* cols,
                                             uint32_t srcB) {
    int tid = threadIdx.x;
    uint32_t st = sb + (uint32_t)(c & 3) * A_STAGE;
#pragma unroll
    for (int i = 0; i < 4; i++) {
        int e = tid + i * 128;                    // 512 chunks = 8 blocks x 64 row-pairs
        int j = e >> 6, r2 = e & 63;
        int col = __ldg(cols + c * 8 + j);
        const char* src = (const char*)g_A2 + ((size_t)col << 16) + srcB + r2 * 16;
        cp_async16(st + j * 1024 + r2 * 16, src);
    }
}

__global__ void __launch_bounds__(128, 1) sgemm_scan_kernel(const int* __restrict__ scale_exp,
                                                            const int* __restrict__ texp,
                                                            float* __restrict__ out) {
    extern __shared__ char smem[];
    const uint32_t sb = smem_u32(smem);
    int tid = threadIdx.x, w = tid >> 5, lane = tid & 31;
    int g = lane >> 2, q = lane & 3;
    int rb = blockIdx.x, b = blockIdx.y;
    uint32_t srcB = (uint32_t)b * 1024;           // byte offset of batch rows in a block
    const uint8_t* cols = g_cols + rb * KCAP;
    int nk = g_nk[rb];
    int nkc = (nk + 7) >> 3;

    // B compact (4KB) -> smem, part of cp.async group 0
    {
        const char* Bg = (const char*)g_Bc + (size_t)rb * 4096;
#pragma unroll
        for (int i = 0; i < 2; i++) {
            int e = tid + i * 128;                // 256 chunks
            int n = e >> 5, o = e & 31;
            cp_async16(sb + B_OFF + n * B_PITCH + o * 16, Bg + n * 512 + o * 16);
        }
    }
    // Prologue: 3 groups always committed
#pragma unroll
    for (int p = 0; p < 3; p++) {
        if (p < nkc) gather_stage(sb, p, cols, srcB);
        cp_commit();
    }

    int acc[2][4] = {{0, 0, 0, 0}, {0, 0, 0, 0}};

    for (int s = 0; s < nkc; s++) {
        cp_wait2();
        __syncthreads();
        if (s + 3 < nkc) gather_stage(sb, s + 3, cols, srcB);
        cp_commit();
        uint32_t st = sb + (uint32_t)(s & 3) * A_STAGE;
#pragma unroll
        for (int kh = 0; kh < 2; kh++) {
            uint32_t b0 = *(const uint32_t*)(smem + B_OFF + g * B_PITCH + s * 64 + kh * 32 + q * 4);
            uint32_t b1 = *(const uint32_t*)(smem + B_OFF + g * B_PITCH + s * 64 + kh * 32 + q * 4 + 16);
            uint32_t bf[2] = {b0, b1};
            int j0 = kh * 4 + (q >> 1);
            int off = (q & 1) * 4;
#pragma unroll
            for (int mt = 0; mt < 2; mt++) {
                int row = w * 32 + mt * 16 + g;
                const char* base = (const char*)smem + (st - sb);
                uint32_t af[4];
                af[0] = *(const uint32_t*)(base + j0 * 1024 + row * 8 + off);
                af[1] = *(const uint32_t*)(base + j0 * 1024 + (row + 8) * 8 + off);
                af[2] = *(const uint32_t*)(base + (j0 + 2) * 1024 + row * 8 + off);
                af[3] = *(const uint32_t*)(base + (j0 + 2) * 1024 + (row + 8) * 8 + off);
                mma_s8(acc[mt], af, bf);
            }
        }
    }

    // Stage C [t][n] into smem fp32 (exact)
    float* sC = (float*)(smem + C_OFF);
#pragma unroll
    for (int mt = 0; mt < 2; mt++) {
        int row = w * 32 + mt * 16 + g;
        sC[row * C_PITCH + 2 * q]           = (float)acc[mt][0];
        sC[row * C_PITCH + 2 * q + 1]       = (float)acc[mt][1];
        sC[(row + 8) * C_PITCH + 2 * q]     = (float)acc[mt][2];
        sC[(row + 8) * C_PITCH + 2 * q + 1] = (float)acc[mt][3];
    }
    __syncthreads();

    // Integrate / fire / reset scan: 8 threads, one per output channel
    uint32_t* sBits = (uint32_t*)(smem + BITS_OFF);
    if (tid < 8) {
        float scale = exp2f((float)scale_exp[rb * 8 + tid]);
        float thr   = exp2f((float)texp[0]);
        float a = 0.0f;
        uint32_t bits[4] = {0, 0, 0, 0};
#pragma unroll 4
        for (int t = 0; t < TT; t++) {
            a = fmaf(sC[t * C_PITCH + tid], scale, a);
            if (a >= thr) { bits[t >> 5] |= 1u << (t & 31); a = 0.0f; }
        }
        sBits[tid * 4 + 0] = bits[0];
        sBits[tid * 4 + 1] = bits[1];
        sBits[tid * 4 + 2] = bits[2];
        sBits[tid * 4 + 3] = bits[3];
    }
    __syncthreads();

    // out[b][rb*8+n][t]
    float* outB = out + ((size_t)b * COUT + rb * 8) * TT;
#pragma unroll
    for (int i = 0; i < 8; i++) {
        int e = tid + i * 128;
        int n = e >> 7, t = e & 127;
        outB[(size_t)n * TT + t] = ((sBits[n * 4 + (t >> 5)] >> (t & 31)) & 1) ? 1.0f : 0.0f;
    }
}

// ---------------------------------------------------------------------------
// Inputs: spikes f32 [64,2048,128], weights f32 [2048,2048], mask f32
// [2048,2048], scale_exp i32 [2048], threshold_exp i32 [1].
// Output: f32 [64,2048,128].
// ---------------------------------------------------------------------------
extern "C" void kernel_launch(void* const* d_in, const int* in_sizes, int n_in,
                              void* d_out, int out_size) {
    const float* spikes    = (const float*)d_in[0];
    const float* weights   = (const float*)d_in[1];
    const float* mask      = (const float*)d_in[2];
    const int*   scale_exp = (const int*)d_in[3];
    const int*   texp      = (const int*)d_in[4];
    float*       out       = (float*)d_out;

    cudaFuncSetAttribute(sgemm_scan_kernel,
                         cudaFuncAttributeMaxDynamicSharedMemorySize, SMEM_G);

    pack_a_kernel<<<dim3(CIN / 64, BB), 256>>>(spikes);
    prep_kernel<<<NRB, 256>>>(weights, mask);
    sgemm_scan_kernel<<<dim3(NRB, BB), 128, SMEM_G>>>(scale_exp, texp, out);
}

// round 5
// speedup vs baseline: 3.8595x; 1.4469x over previous
#include <cuda_runtime.h>
#include <stdint.h>

// Problem shape (fixed)
#define BB    64
#define TT    128
#define CIN   2048
#define COUT  2048
#define NRB   256          // COUT/8 block-rows
#define NCB   256          // CIN/8  block-cols
#define KCAP  64           // max kept blocks per block-row (Binom(256,0.1) max ~45)
#define MB    4            // batches per GEMM CTA
#define MROWS (MB * TT)    // 512

#define B_PITCH 528        // bytes per n-row in smem B (512 data + 16 pad)
#define C_PITCH 9          // fp32 words per staged C row

// Scratch (static device globals — no runtime allocation)
__device__ __align__(16) uint8_t g_packed[(size_t)BB * NCB * TT]; // 2MB [b][cb][t] bitmask
__device__ __align__(16) int8_t  g_Bc[(size_t)NRB * 8 * KCAP * 8];// 1MB [rb][n][k_compact]
__device__ uint8_t g_cols[NRB * KCAP];
__device__ int     g_nk[NRB];

// ---------------------------------------------------------------------------
// helpers
// ---------------------------------------------------------------------------
__device__ __forceinline__ void mma_s8(int* c, const uint32_t* a, const uint32_t* b) {
    asm volatile(
        "mma.sync.aligned.m16n8k32.row.col.s32.s8.s8.s32 "
        "{%0,%1,%2,%3}, {%4,%5,%6,%7}, {%8,%9}, {%0,%1,%2,%3};"
        : "+r"(c[0]), "+r"(c[1]), "+r"(c[2]), "+r"(c[3])
        : "r"(a[0]), "r"(a[1]), "r"(a[2]), "r"(a[3]), "r"(b[0]), "r"(b[1]));
}
// expand 4 bits (at bit offset sh, sh in {0,4}) to 4 bytes of 0/1
__device__ __forceinline__ uint32_t expand_nib(uint32_t byte, uint32_t sh) {
    return (((byte >> sh) & 0xFu) * 0x00204081u) & 0x01010101u;
}

// ---------------------------------------------------------------------------
// Kernel 1: spikes [b][c][t] f32 -> g_packed[b][cb][t] bit j = spike(cb*8+j, t)
// Grid (CIN/64=32, BB); 256 threads.
// ---------------------------------------------------------------------------
__global__ void __launch_bounds__(256) pack_a_kernel(const float* __restrict__ spikes) {
    __shared__ float s[64][132];
    int b = blockIdx.y, c0 = blockIdx.x * 64, tid = threadIdx.x;
    const float* sp = spikes + ((size_t)b * CIN + c0) * TT;
#pragma unroll
    for (int i = 0; i < 8; i++) {                 // 2048 float4 loads
        int e = tid + i * 256;
        int c = e >> 5, t4 = e & 31;
        float4 v = *(const float4*)(sp + (size_t)c * TT + t4 * 4);
        *(float4*)&s[c][t4 * 4] = v;
    }
    __syncthreads();
    int cb0 = blockIdx.x * 8;
#pragma unroll
    for (int i = 0; i < 4; i++) {                 // 1024 byte writes
        int e = tid + i * 256;
        int cb = e >> 7, t = e & 127;
        uint32_t byte = 0;
#pragma unroll
        for (int j = 0; j < 8; j++)
            byte |= (s[cb * 8 + j][t] > 0.5f ? 1u : 0u) << j;
        g_packed[((size_t)b * NCB + cb0 + cb) * TT + t] = (uint8_t)byte;
    }
}

// ---------------------------------------------------------------------------
// Kernel 2: per block-row: detect kept 8x8 blocks (mask is uniform per block,
// probe one element), compact weights.  One CTA of 256 per rb.
// ---------------------------------------------------------------------------
__global__ void __launch_bounds__(256) prep_kernel(const float* __restrict__ W,
                                                   const float* __restrict__ M) {
    int rb = blockIdx.x, tid = threadIdx.x;
    __shared__ uint8_t keptf[NCB];
    __shared__ uint8_t colss[KCAP];
    __shared__ int nks;

    keptf[tid] = (M[(size_t)(rb * 8) * CIN + tid * 8] != 0.0f) ? 1 : 0;
    __syncthreads();
    if (tid == 0) {
        int n = 0;
        for (int c = 0; c < NCB; c++)
            if (keptf[c] && n < KCAP) colss[n++] = (uint8_t)c;
        nks = n;
        g_nk[rb] = n;
        for (int k = n; k < KCAP; k++) colss[k] = 0;
    }
    __syncthreads();
    if (tid < KCAP) g_cols[rb * KCAP + tid] = colss[tid];

    int nk8 = nks * 8;
    for (int idx = tid; idx < 8 * KCAP * 8; idx += 256) {
        int n = idx >> 9, kk = idx & 511;
        int8_t val = 0;
        if (kk < nk8) {
            int col = colss[kk >> 3], jj = kk & 7;
            val = (int8_t)__float2int_rn(W[(size_t)(rb * 8 + n) * CIN + col * 8 + jj]);
        }
        g_Bc[(size_t)rb * 4096 + n * 512 + kk] = val;
    }
}

// ---------------------------------------------------------------------------
// Kernel 3: block-sparse int8 MMA + fused integrate/fire/reset scan.
// CTA = (rb, batch-group of 4): M=512, N=8, K = nk*8 (compacted).
// 8 warps; warp w owns rows w*64..w*64+63 (batch w/2).  A loaded as bits
// straight from L1/L2 and nibble-expanded into MMA fragments.
// ---------------------------------------------------------------------------
__global__ void __launch_bounds__(256, 4) sgemm_scan_kernel(const int* __restrict__ scale_exp,
                                                            const int* __restrict__ texp,
                                                            float* __restrict__ out) {
    __shared__ __align__(16) uint8_t sB[8 * B_PITCH];
    __shared__ uint8_t scol[KCAP];
    __shared__ float   sC[MROWS * C_PITCH];
    __shared__ uint32_t sBits[MB * 8 * 4];

    int tid = threadIdx.x, w = tid >> 5, lane = tid & 31;
    int g = lane >> 2, q = lane & 3;
    int rb = blockIdx.x;
    int b0 = blockIdx.y * MB;

    // Stage B (4KB) + column list
    {
        const uint4* Bg = (const uint4*)(g_Bc + (size_t)rb * 4096);
        int n = tid >> 5, o = tid & 31;
        *(uint4*)(sB + n * B_PITCH + o * 16) = __ldg(Bg + n * 32 + o);
        if (tid < KCAP / 4)
            *(uint32_t*)(scol + tid * 4) = __ldg((const uint32_t*)(g_cols + rb * KCAP) + tid);
    }
    int nk = g_nk[rb];
    int nkc = (nk + 3) >> 2;
    __syncthreads();

    int acc[4][4];
#pragma unroll
    for (int i = 0; i < 4; i++)
#pragma unroll
        for (int j = 0; j < 4; j++) acc[i][j] = 0;

    // per-warp A base: batch bi = w>>1, local row base (w&1)*64 + g
    const uint8_t* pk = g_packed + ((size_t)(b0 + (w >> 1)) * NCB) * TT;
    const int tbase = (w & 1) * 64 + g;
    const uint32_t sh = (q & 1) * 4;

    for (int it = 0; it < nkc; it++) {
        int kc = it * 4;
        uint32_t bf[2];
        bf[0] = *(const uint32_t*)(sB + g * B_PITCH + kc * 8 + q * 4);
        bf[1] = *(const uint32_t*)(sB + g * B_PITCH + kc * 8 + q * 4 + 16);
        const uint8_t* pA = pk + (int)scol[kc + (q >> 1)] * TT;
        const uint8_t* pB2 = pk + (int)scol[kc + 2 + (q >> 1)] * TT;
#pragma unroll
        for (int mt = 0; mt < 4; mt++) {
            int r = tbase + mt * 16;
            uint32_t af[4];
            af[0] = expand_nib(__ldg(pA + r), sh);
            af[1] = expand_nib(__ldg(pA + r + 8), sh);
            af[2] = expand_nib(__ldg(pB2 + r), sh);
            af[3] = expand_nib(__ldg(pB2 + r + 8), sh);
            mma_s8(acc[mt], af, bf);
        }
    }

    // Stage C (rows = global m, cols = n) into smem fp32 (exact, |acc|<2^18)
#pragma unroll
    for (int mt = 0; mt < 4; mt++) {
        int row = w * 64 + mt * 16 + g;
        sC[row * C_PITCH + 2 * q]           = (float)acc[mt][0];
        sC[row * C_PITCH + 2 * q + 1]       = (float)acc[mt][1];
        sC[(row + 8) * C_PITCH + 2 * q]     = (float)acc[mt][2];
        sC[(row + 8) * C_PITCH + 2 * q + 1] = (float)acc[mt][3];
    }
    __syncthreads();

    // Integrate / fire / reset: 32 scans (4 batches x 8 channels)
    if (tid < MB * 8) {
        int ch = tid & 7, bi = tid >> 3;
        float scale = exp2f((float)scale_exp[rb * 8 + ch]);
        float thr   = exp2f((float)texp[0]);
        float a = 0.0f;
        uint32_t bits[4] = {0, 0, 0, 0};
        const float* c = sC + (size_t)bi * TT * C_PITCH + ch;
#pragma unroll 4
        for (int t = 0; t < TT; t++) {
            a = fmaf(c[t * C_PITCH], scale, a);
            if (a >= thr) { bits[t >> 5] |= 1u << (t & 31); a = 0.0f; }
        }
        sBits[tid * 4 + 0] = bits[0];
        sBits[tid * 4 + 1] = bits[1];
        sBits[tid * 4 + 2] = bits[2];
        sBits[tid * 4 + 3] = bits[3];
    }
    __syncthreads();

    // Output: out[b0+bi][rb*8+ch][t], float4 per thread x4
#pragma unroll
    for (int i = 0; i < 4; i++) {
        int e = tid + i * 256;
        int r = e >> 5, t4 = e & 31;       // r = bi*8+ch
        int bi = r >> 3, ch = r & 7;
        uint32_t word = sBits[r * 4 + (t4 >> 3)];
        float4 v;
        v.x = (word >> ((t4 * 4 + 0) & 31)) & 1 ? 1.0f : 0.0f;
        v.y = (word >> ((t4 * 4 + 1) & 31)) & 1 ? 1.0f : 0.0f;
        v.z = (word >> ((t4 * 4 + 2) & 31)) & 1 ? 1.0f : 0.0f;
        v.w = (word >> ((t4 * 4 + 3) & 31)) & 1 ? 1.0f : 0.0f;
        *(float4*)(out + ((size_t)(b0 + bi) * COUT + rb * 8 + ch) * TT + t4 * 4) = v;
    }
}

// ---------------------------------------------------------------------------
// Inputs: spikes f32 [64,2048,128], weights f32 [2048,2048], mask f32
// [2048,2048], scale_exp i32 [2048], threshold_exp i32 [1].
// Output: f32 [64,2048,128].
// ---------------------------------------------------------------------------
extern "C" void kernel_launch(void* const* d_in, const int* in_sizes, int n_in,
                              void* d_out, int out_size) {
    const float* spikes    = (const float*)d_in[0];
    const float* weights   = (const float*)d_in[1];
    const float* mask      = (const float*)d_in[2];
    const int*   scale_exp = (const int*)d_in[3];
    const int*   texp      = (const int*)d_in[4];
    float*       out       = (float*)d_out;

    pack_a_kernel<<<dim3(CIN / 64, BB), 256>>>(spikes);
    prep_kernel<<<NRB, 256>>>(weights, mask);
    sgemm_scan_kernel<<<dim3(NRB, BB / MB), 256>>>(scale_exp, texp, out);
}

// round 6
// speedup vs baseline: 4.2829x; 1.1097x over previous
#include <cuda_runtime.h>
#include <stdint.h>

// Problem shape (fixed)
#define BB    64
#define TT    128
#define CIN   2048
#define COUT  2048
#define NRB   256          // COUT/8 block-rows
#define NCB   256          // CIN/8  block-cols
#define KCAP  64           // max kept blocks per block-row (Binom(256,0.1) max ~45)
#define MB    4            // batches per GEMM CTA
#define MROWS (MB * TT)    // 512

#define B_PITCH 528        // bytes per n-row in smem B (512 data + 16 pad)
#define C_PITCH 9          // fp32 words per staged C row
#define COLSTRIDE ((size_t)BB * 128)   // bytes per block-column in g_packed2

// Scratch (static device globals — no runtime allocation)
// g_packed2[cb][b][off]: off = (t&~15)|((t&7)<<1)|((t>>3)&1) → rows (r,r+8) adjacent
__device__ __align__(16) uint8_t g_packed2[(size_t)NCB * BB * TT]; // 2MB
__device__ __align__(16) int8_t  g_Bc[(size_t)NRB * 8 * KCAP * 8]; // 1MB, interleaved k-order
__device__ uint8_t g_cols[NRB * KCAP];
__device__ int     g_nk[NRB];

// ---------------------------------------------------------------------------
// helpers
// ---------------------------------------------------------------------------
__device__ __forceinline__ void mma_s8(int* c, const uint32_t* a, const uint32_t* b) {
    asm volatile(
        "mma.sync.aligned.m16n8k32.row.col.s32.s8.s8.s32 "
        "{%0,%1,%2,%3}, {%4,%5,%6,%7}, {%8,%9}, {%0,%1,%2,%3};"
        : "+r"(c[0]), "+r"(c[1]), "+r"(c[2]), "+r"(c[3])
        : "r"(a[0]), "r"(a[1]), "r"(a[2]), "r"(a[3]), "r"(b[0]), "r"(b[1]));
}
// expand 4 bits at offset sh to 4 bytes of 0/1
__device__ __forceinline__ uint32_t expand_nib(uint32_t v, uint32_t sh) {
    return (((v >> sh) & 0xFu) * 0x00204081u) & 0x01010101u;
}

// ---------------------------------------------------------------------------
// Kernel 1: spikes [b][c][t] f32 -> g_packed2 pair layout.  Grid (NCB/2, BB),
// 256 threads; all loads warp-coalesced 128B, stores 32B/warp.
// ---------------------------------------------------------------------------
__global__ void __launch_bounds__(256) pack_a_kernel(const float* __restrict__ spikes) {
    int b = blockIdx.y;
    int cb = blockIdx.x * 2 + (threadIdx.x >> 7);
    int t  = threadIdx.x & 127;
    const float* sp = spikes + ((size_t)b * CIN + cb * 8) * TT + t;
    uint32_t byte = 0;
#pragma unroll
    for (int j = 0; j < 8; j++)
        byte |= (__ldg(sp + (size_t)j * TT) > 0.5f ? 1u : 0u) << j;
    int off = (t & ~15) | ((t & 7) << 1) | ((t >> 3) & 1);
    g_packed2[(size_t)cb * COLSTRIDE + b * 128 + off] = (uint8_t)byte;
}

// ---------------------------------------------------------------------------
// Kernel 2: per block-row: detect kept blocks (mask uniform per 8x8 block ->
// probe one element), compact weights in the interleaved k-order:
//   within each 32-k chunk: j = (w5>>2)&3 (block), c = (w5&3)+4*(w5>>4)
// ---------------------------------------------------------------------------
__global__ void __launch_bounds__(256) prep_kernel(const float* __restrict__ W,
                                                   const float* __restrict__ M) {
    int rb = blockIdx.x, tid = threadIdx.x;
    __shared__ uint8_t keptf[NCB];
    __shared__ uint8_t colss[KCAP];
    __shared__ int nks;

    keptf[tid] = (M[(size_t)(rb * 8) * CIN + tid * 8] != 0.0f) ? 1 : 0;
    __syncthreads();
    if (tid == 0) {
        int n = 0;
        for (int c = 0; c < NCB; c++)
            if (keptf[c] && n < KCAP) colss[n++] = (uint8_t)c;
        nks = n;
        g_nk[rb] = n;
        for (int k = n; k < KCAP; k++) colss[k] = 0;
    }
    __syncthreads();
    if (tid < KCAP) g_cols[rb * KCAP + tid] = colss[tid];

    int nk = nks;
    for (int idx = tid; idx < 8 * KCAP * 8; idx += 256) {
        int n = idx >> 9, kk = idx & 511;
        int chunk = kk >> 5, w5 = kk & 31;
        int j = (w5 >> 2) & 3;
        int c = (w5 & 3) + 4 * (w5 >> 4);
        int blk = chunk * 4 + j;
        int8_t val = 0;
        if (blk < nk)
            val = (int8_t)__float2int_rn(W[(size_t)(rb * 8 + n) * CIN + colss[blk] * 8 + c]);
        g_Bc[(size_t)rb * 4096 + n * 512 + kk] = val;
    }
}

// ---------------------------------------------------------------------------
// Kernel 3: block-sparse int8 MMA + fused integrate/fire/reset scan.
// CTA = (rb, 4-batch group): M=512, N=8, K = nk*8 compacted.
// Thread (g,q): A fragment of each MMA = ONE u16 from g_packed2.
// ---------------------------------------------------------------------------
__global__ void __launch_bounds__(256, 4) sgemm_scan_kernel(const int* __restrict__ scale_exp,
                                                            const int* __restrict__ texp,
                                                            float* __restrict__ out) {
    __shared__ __align__(16) uint8_t sB[8 * B_PITCH];
    __shared__ uint8_t scol[KCAP];
    __shared__ float   sC[MROWS * C_PITCH];
    __shared__ uint32_t sBits[MB * 8 * 4];

    int tid = threadIdx.x, w = tid >> 5, lane = tid & 31;
    int g = lane >> 2, q = lane & 3;
    int rb = blockIdx.x;
    int b0 = blockIdx.y * MB;

    // Stage B (4KB) + column list
    {
        const uint4* Bg = (const uint4*)(g_Bc + (size_t)rb * 4096);
        int n = tid >> 5, o = tid & 31;
        *(uint4*)(sB + n * B_PITCH + o * 16) = __ldg(Bg + n * 32 + o);
        if (tid < KCAP / 4)
            *(uint32_t*)(scol + tid * 4) = __ldg((const uint32_t*)(g_cols + rb * KCAP) + tid);
    }
    int nk = g_nk[rb];
    int nkc = (nk + 3) >> 2;
    __syncthreads();

    int acc[4][4];
#pragma unroll
    for (int i = 0; i < 4; i++)
#pragma unroll
        for (int j = 0; j < 4; j++) acc[i][j] = 0;

    // warp w: batch bi = w>>1, tiles (w&1)*4 .. +3; thread q owns block-col it*4+q
    const uint8_t* base = g_packed2 + (size_t)(b0 + (w >> 1)) * 128 + (w & 1) * 64 + g * 2;
    const uint8_t* sBrow = sB + g * B_PITCH;

    // prefetch iteration 0
    uint32_t v[4], vn[4];
    {
        const uint8_t* pA = base + (size_t)scol[q] * COLSTRIDE;
#pragma unroll
        for (int mt = 0; mt < 4; mt++)
            v[mt] = *(const uint16_t*)(pA + mt * 16);
    }

    for (int it = 0; it < nkc; it++) {
        if (it + 1 < nkc) {
            const uint8_t* pA = base + (size_t)scol[(it + 1) * 4 + q] * COLSTRIDE;
#pragma unroll
            for (int mt = 0; mt < 4; mt++)
                vn[mt] = *(const uint16_t*)(pA + mt * 16);
        }
        uint32_t bf[2];
        bf[0] = *(const uint32_t*)(sBrow + it * 32 + q * 4);
        bf[1] = *(const uint32_t*)(sBrow + it * 32 + q * 4 + 16);
#pragma unroll
        for (int mt = 0; mt < 4; mt++) {
            uint32_t af[4];
            af[0] = expand_nib(v[mt], 0);   // row r,   ch 0..3
            af[1] = expand_nib(v[mt], 8);   // row r+8, ch 0..3
            af[2] = expand_nib(v[mt], 4);   // row r,   ch 4..7
            af[3] = expand_nib(v[mt], 12);  // row r+8, ch 4..7
            mma_s8(acc[mt], af, bf);
        }
#pragma unroll
        for (int mt = 0; mt < 4; mt++) v[mt] = vn[mt];
    }

    // Stage C (rows = m, cols = n) into smem fp32 (exact, |acc|<2^18)
#pragma unroll
    for (int mt = 0; mt < 4; mt++) {
        int row = w * 64 + mt * 16 + g;
        sC[row * C_PITCH + 2 * q]           = (float)acc[mt][0];
        sC[row * C_PITCH + 2 * q + 1]       = (float)acc[mt][1];
        sC[(row + 8) * C_PITCH + 2 * q]     = (float)acc[mt][2];
        sC[(row + 8) * C_PITCH + 2 * q + 1] = (float)acc[mt][3];
    }
    __syncthreads();

    // Integrate / fire / reset: 32 scans (4 batches x 8 channels)
    if (tid < MB * 8) {
        int ch = tid & 7, bi = tid >> 3;
        float scale = exp2f((float)scale_exp[rb * 8 + ch]);
        float thr   = exp2f((float)texp[0]);
        float a = 0.0f;
        uint32_t bits[4] = {0, 0, 0, 0};
        const float* c = sC + (size_t)bi * TT * C_PITCH + ch;
#pragma unroll 4
        for (int t = 0; t < TT; t++) {
            a = fmaf(c[t * C_PITCH], scale, a);
            if (a >= thr) { bits[t >> 5] |= 1u << (t & 31); a = 0.0f; }
        }
        sBits[tid * 4 + 0] = bits[0];
        sBits[tid * 4 + 1] = bits[1];
        sBits[tid * 4 + 2] = bits[2];
        sBits[tid * 4 + 3] = bits[3];
    }
    __syncthreads();

    // Output: out[b0+bi][rb*8+ch][t], float4 per thread x4
#pragma unroll
    for (int i = 0; i < 4; i++) {
        int e = tid + i * 256;
        int r = e >> 5, t4 = e & 31;       // r = bi*8+ch
        int bi = r >> 3, ch = r & 7;
        uint32_t word = sBits[r * 4 + (t4 >> 3)];
        float4 vv;
        vv.x = (word >> ((t4 * 4 + 0) & 31)) & 1 ? 1.0f : 0.0f;
        vv.y = (word >> ((t4 * 4 + 1) & 31)) & 1 ? 1.0f : 0.0f;
        vv.z = (word >> ((t4 * 4 + 2) & 31)) & 1 ? 1.0f : 0.0f;
        vv.w = (word >> ((t4 * 4 + 3) & 31)) & 1 ? 1.0f : 0.0f;
        *(float4*)(out + ((size_t)(b0 + bi) * COUT + rb * 8 + ch) * TT + t4 * 4) = vv;
    }
}

// ---------------------------------------------------------------------------
// Inputs: spikes f32 [64,2048,128], weights f32 [2048,2048], mask f32
// [2048,2048], scale_exp i32 [2048], threshold_exp i32 [1].
// Output: f32 [64,2048,128].
// ---------------------------------------------------------------------------
extern "C" void kernel_launch(void* const* d_in, const int* in_sizes, int n_in,
                              void* d_out, int out_size) {
    const float* spikes    = (const float*)d_in[0];
    const float* weights   = (const float*)d_in[1];
    const float* mask      = (const float*)d_in[2];
    const int*   scale_exp = (const int*)d_in[3];
    const int*   texp      = (const int*)d_in[4];
    float*       out       = (float*)d_out;

    pack_a_kernel<<<dim3(NCB / 2, BB), 256>>>(spikes);
    prep_kernel<<<NRB, 256>>>(weights, mask);
    sgemm_scan_kernel<<<dim3(NRB, BB / MB), 256>>>(scale_exp, texp, out);
}

// round 7
// speedup vs baseline: 4.9249x; 1.1499x over previous
#include <cuda_runtime.h>
#include <stdint.h>

// Problem shape (fixed)
#define BB    64
#define TT    128
#define CIN   2048
#define COUT  2048
#define NRB   256          // COUT/8 block-rows
#define NCB   256          // CIN/8  block-cols
#define KCAP  64           // max kept blocks per block-row
#define MB    4            // batches per GEMM CTA
#define MROWS (MB * TT)    // 512

#define B_PITCH 528        // bytes per n-row in smem B (512 data + 16 pad)
#define A_PITCH 528        // bytes per block-col in smem A (512 data + 16 pad)
#define C_PITCH 9          // fp32 words per staged C row
#define COLSTRIDE ((size_t)BB * 128)   // bytes per block-column in g_packed2

// Dynamic smem layout (A region reused for C staging after the mainloop)
#define SA_OFF    0
#define SA_BYTES  (KCAP * A_PITCH)            // 33792 (>= MROWS*C_PITCH*4 = 18432)
#define SB_OFF    SA_BYTES
#define SBITS_OFF (SB_OFF + 8 * B_PITCH)      // 38016
#define SMEM_G    (SBITS_OFF + 512)           // 38528 (< 48KB, no attribute needed)

// Scratch (static device globals — no runtime allocation)
// g_packed2[cb][b][off]: off = (t&~15)|((t&7)<<1)|((t>>3)&1) → rows (r,r+8) adjacent
__device__ __align__(16) uint8_t g_packed2[(size_t)NCB * BB * TT]; // 2MB
__device__ __align__(16) int8_t  g_Bc[(size_t)NRB * 8 * KCAP * 8]; // 1MB, interleaved k-order
__device__ uint8_t g_cols[NRB * KCAP];
__device__ int     g_nk[NRB];

// ---------------------------------------------------------------------------
// helpers
// ---------------------------------------------------------------------------
__device__ __forceinline__ uint32_t smem_u32(const void* p) {
    uint32_t a;
    asm("{ .reg .u64 t; cvta.to.shared.u64 t, %1; cvt.u32.u64 %0, t; }" : "=r"(a) : "l"(p));
    return a;
}
__device__ __forceinline__ void cp_async16(uint32_t dst, const void* src) {
    asm volatile("cp.async.cg.shared.global [%0], [%1], 16;" :: "r"(dst), "l"(src) : "memory");
}
__device__ __forceinline__ void cp_commit_wait0() {
    asm volatile("cp.async.commit_group;" ::: "memory");
    asm volatile("cp.async.wait_group 0;" ::: "memory");
}
__device__ __forceinline__ void mma_s8(int* c, const uint32_t* a, const uint32_t* b) {
    asm volatile(
        "mma.sync.aligned.m16n8k32.row.col.s32.s8.s8.s32 "
        "{%0,%1,%2,%3}, {%4,%5,%6,%7}, {%8,%9}, {%0,%1,%2,%3};"
        : "+r"(c[0]), "+r"(c[1]), "+r"(c[2]), "+r"(c[3])
        : "r"(a[0]), "r"(a[1]), "r"(a[2]), "r"(a[3]), "r"(b[0]), "r"(b[1]));
}
// expand 4 bits at offset sh to 4 bytes of 0/1
__device__ __forceinline__ uint32_t expand_nib(uint32_t v, uint32_t sh) {
    return (((v >> sh) & 0xFu) * 0x00204081u) & 0x01010101u;
}

// ---------------------------------------------------------------------------
// Kernel 1: spikes [b][c][t] f32 -> g_packed2 pair layout.  Grid (NCB/2, BB),
// 256 threads; all loads warp-coalesced.
// ---------------------------------------------------------------------------
__global__ void __launch_bounds__(256) pack_a_kernel(const float* __restrict__ spikes) {
    int b = blockIdx.y;
    int cb = blockIdx.x * 2 + (threadIdx.x >> 7);
    int t  = threadIdx.x & 127;
    const float* sp = spikes + ((size_t)b * CIN + cb * 8) * TT + t;
    uint32_t byte = 0;
#pragma unroll
    for (int j = 0; j < 8; j++)
        byte |= (__ldg(sp + (size_t)j * TT) > 0.5f ? 1u : 0u) << j;
    int off = (t & ~15) | ((t & 7) << 1) | ((t >> 3) & 1);
    g_packed2[(size_t)cb * COLSTRIDE + b * 128 + off] = (uint8_t)byte;
}

// ---------------------------------------------------------------------------
// Kernel 2: per block-row: detect kept blocks (mask uniform per 8x8 block ->
// probe one element), compact weights in the interleaved k-order:
//   within each 32-k chunk: j = (w5>>2)&3 (block), c = (w5&3)+4*(w5>>4)
// ---------------------------------------------------------------------------
__global__ void __launch_bounds__(256) prep_kernel(const float* __restrict__ W,
                                                   const float* __restrict__ M) {
    int rb = blockIdx.x, tid = threadIdx.x;
    __shared__ uint8_t keptf[NCB];
    __shared__ uint8_t colss[KCAP];
    __shared__ int nks;

    keptf[tid] = (M[(size_t)(rb * 8) * CIN + tid * 8] != 0.0f) ? 1 : 0;
    __syncthreads();
    if (tid == 0) {
        int n = 0;
        for (int c = 0; c < NCB; c++)
            if (keptf[c] && n < KCAP) colss[n++] = (uint8_t)c;
        nks = n;
        g_nk[rb] = n;
        for (int k = n; k < KCAP; k++) colss[k] = 0;
    }
    __syncthreads();
    if (tid < KCAP) g_cols[rb * KCAP + tid] = colss[tid];

    int nk = nks;
    for (int idx = tid; idx < 8 * KCAP * 8; idx += 256) {
        int n = idx >> 9, kk = idx & 511;
        int chunk = kk >> 5, w5 = kk & 31;
        int j = (w5 >> 2) & 3;
        int c = (w5 & 3) + 4 * (w5 >> 4);
        int blk = chunk * 4 + j;
        int8_t val = 0;
        if (blk < nk)
            val = (int8_t)__float2int_rn(W[(size_t)(rb * 8 + n) * CIN + colss[blk] * 8 + c]);
        g_Bc[(size_t)rb * 4096 + n * 512 + kk] = val;
    }
}

// ---------------------------------------------------------------------------
// Kernel 3: block-sparse int8 MMA + fused integrate/fire/reset scan.
// CTA = (rb, 4-batch group): M=512, N=8, K = nk*8 compacted.
// A (nk block-cols x 512B) staged to smem by one coalesced cp.async burst;
// mainloop is pure smem: LDS.U16 per fragment, expand, MMA.
// ---------------------------------------------------------------------------
__global__ void __launch_bounds__(256) sgemm_scan_kernel(const int* __restrict__ scale_exp,
                                                         const int* __restrict__ texp,
                                                         float* __restrict__ out) {
    extern __shared__ __align__(16) uint8_t smem[];
    const uint32_t sbA = smem_u32(smem);

    int tid = threadIdx.x, w = tid >> 5, lane = tid & 31;
    int g = lane >> 2, q = lane & 3;
    int rb = blockIdx.x;
    int b0 = blockIdx.y * MB;

    int nk = __ldg(&g_nk[rb]);
    int nkc = (nk + 3) >> 2;
    const uint8_t* colp = g_cols + rb * KCAP;

    // Stage B (4KB, 256 chunks) + A (nk*512B, coalesced 512B per kept col)
    {
        const char* Bg = (const char*)g_Bc + (size_t)rb * 4096;
        int n = tid >> 5, o = tid & 31;
        cp_async16(sbA + SB_OFF + n * B_PITCH + o * 16, Bg + n * 512 + o * 16);

        int nk32 = nk * 32;
        const char* Ag = (const char*)g_packed2 + (size_t)b0 * 128;
        for (int e = tid; e < nk32; e += 256) {
            int blk = e >> 5, o2 = e & 31;
            int col = __ldg(colp + blk);
            cp_async16(sbA + SA_OFF + blk * A_PITCH + o2 * 16,
                       Ag + (size_t)col * COLSTRIDE + o2 * 16);
        }
    }
    cp_commit_wait0();
    __syncthreads();

    int acc[4][4];
#pragma unroll
    for (int i = 0; i < 4; i++)
#pragma unroll
        for (int j = 0; j < 4; j++) acc[i][j] = 0;

    // warp w: batch bi = w>>1, row-half (w&1); thread q owns block-col it*4+q
    const uint8_t* sA = smem + SA_OFF + (w >> 1) * 128 + (w & 1) * 64 + g * 2;
    const uint8_t* sBrow = smem + SB_OFF + g * B_PITCH;

    for (int it = 0; it < nkc; it++) {
        uint32_t bf[2];
        bf[0] = *(const uint32_t*)(sBrow + it * 32 + q * 4);
        bf[1] = *(const uint32_t*)(sBrow + it * 32 + q * 4 + 16);
        const uint8_t* pA = sA + (it * 4 + q) * A_PITCH;
#pragma unroll
        for (int mt = 0; mt < 4; mt++) {
            uint32_t v = *(const uint16_t*)(pA + mt * 16);
            uint32_t af[4];
            af[0] = expand_nib(v, 0);   // row r,   ch 0..3
            af[1] = expand_nib(v, 8);   // row r+8, ch 0..3
            af[2] = expand_nib(v, 4);   // row r,   ch 4..7
            af[3] = expand_nib(v, 12);  // row r+8, ch 4..7
            mma_s8(acc[mt], af, bf);
        }
    }
    __syncthreads();   // A region dead; reuse as C staging

    // Stage C (rows = m, cols = n) into smem fp32 (exact, |acc|<2^18)
    float* sC = (float*)(smem + SA_OFF);
#pragma unroll
    for (int mt = 0; mt < 4; mt++) {
        int row = w * 64 + mt * 16 + g;
        sC[row * C_PITCH + 2 * q]           = (float)acc[mt][0];
        sC[row * C_PITCH + 2 * q + 1]       = (float)acc[mt][1];
        sC[(row + 8) * C_PITCH + 2 * q]     = (float)acc[mt][2];
        sC[(row + 8) * C_PITCH + 2 * q + 1] = (float)acc[mt][3];
    }
    __syncthreads();

    // Integrate / fire / reset: 32 scans (4 batches x 8 channels)
    uint32_t* sBits = (uint32_t*)(smem + SBITS_OFF);
    if (tid < MB * 8) {
        int ch = tid & 7, bi = tid >> 3;
        float scale = exp2f((float)scale_exp[rb * 8 + ch]);
        float thr   = exp2f((float)texp[0]);
        float a = 0.0f;
        uint32_t bits[4] = {0, 0, 0, 0};
        const float* c = sC + (size_t)bi * TT * C_PITCH + ch;
#pragma unroll 4
        for (int t = 0; t < TT; t++) {
            a = fmaf(c[t * C_PITCH], scale, a);
            if (a >= thr) { bits[t >> 5] |= 1u << (t & 31); a = 0.0f; }
        }
        sBits[tid * 4 + 0] = bits[0];
        sBits[tid * 4 + 1] = bits[1];
        sBits[tid * 4 + 2] = bits[2];
        sBits[tid * 4 + 3] = bits[3];
    }
    __syncthreads();

    // Output: out[b0+bi][rb*8+ch][t], float4 per thread x4
#pragma unroll
    for (int i = 0; i < 4; i++) {
        int e = tid + i * 256;
        int r = e >> 5, t4 = e & 31;       // r = bi*8+ch
        int bi = r >> 3, ch = r & 7;
        uint32_t word = sBits[r * 4 + (t4 >> 3)];
        float4 vv;
        vv.x = (word >> ((t4 * 4 + 0) & 31)) & 1 ? 1.0f : 0.0f;
        vv.y = (word >> ((t4 * 4 + 1) & 31)) & 1 ? 1.0f : 0.0f;
        vv.z = (word >> ((t4 * 4 + 2) & 31)) & 1 ? 1.0f : 0.0f;
        vv.w = (word >> ((t4 * 4 + 3) & 31)) & 1 ? 1.0f : 0.0f;
        *(float4*)(out + ((size_t)(b0 + bi) * COUT + rb * 8 + ch) * TT + t4 * 4) = vv;
    }
}

// ---------------------------------------------------------------------------
// Inputs: spikes f32 [64,2048,128], weights f32 [2048,2048], mask f32
// [2048,2048], scale_exp i32 [2048], threshold_exp i32 [1].
// Output: f32 [64,2048,128].
// ---------------------------------------------------------------------------
extern "C" void kernel_launch(void* const* d_in, const int* in_sizes, int n_in,
                              void* d_out, int out_size) {
    const float* spikes    = (const float*)d_in[0];
    const float* weights   = (const float*)d_in[1];
    const float* mask      = (const float*)d_in[2];
    const int*   scale_exp = (const int*)d_in[3];
    const int*   texp      = (const int*)d_in[4];
    float*       out       = (float*)d_out;

    pack_a_kernel<<<dim3(NCB / 2, BB), 256>>>(spikes);
    prep_kernel<<<NRB, 256>>>(weights, mask);
    sgemm_scan_kernel<<<dim3(NRB, BB / MB), 256, SMEM_G>>>(scale_exp, texp, out);
}